// round 12
// baseline (speedup 1.0000x reference)
#include <cuda_runtime.h>
#include <cuda_fp16.h>
#include <cstdint>

#define NN   8192
#define FIN  512
#define FOUT 256

// ---- scratch (static device memory; no allocation) ----
__device__ __align__(16) float g_h [NN * FOUT];          // fp32 h
__device__ __align__(16) __half g_hT[FOUT * NN];         // fp16 h transposed [n][j]
__device__ __align__(16) float g_s1r[NN];
__device__ __align__(16) float g_s2r[NN];
__device__ __align__(16) float2 g_e1[NN];                // (exp(s1-m), exp(.2 s1-m))
__device__ __align__(16) float2 g_e2[NN];                // (exp(s2), exp(.2 s2))
__device__ __align__(16) uint32_t g_mask[NN * 256];      // bit-packed adj
__device__ __align__(16) float g_dpart[2 * NN * FOUT];
__device__ __align__(16) float g_z[2 * NN];

// ============================================================
// helpers
// ============================================================
__device__ __forceinline__ uint32_t smem_u32(const void* p) {
    uint32_t a;
    asm("{ .reg .u64 t; cvta.to.shared.u64 t, %1; cvt.u32.u64 %0, t; }" : "=r"(a) : "l"(p));
    return a;
}
__device__ __forceinline__ unsigned long long pack2(float lo, float hi) {
    unsigned long long r;
    asm("mov.b64 %0, {%1, %2};" : "=l"(r) : "f"(lo), "f"(hi));
    return r;
}
__device__ __forceinline__ void unpack2(unsigned long long v, float& lo, float& hi) {
    asm("mov.b64 {%0, %1}, %2;" : "=f"(lo), "=f"(hi) : "l"(v));
}
__device__ __forceinline__ uint32_t f16x2_pack(float hi, float lo) {
    uint32_t r;
    asm("cvt.rn.f16x2.f32 %0, %1, %2;" : "=r"(r) : "f"(hi), "f"(lo));
    return r;
}

// ============================================================
// Kernel 1: fused (h = input @ W  [128 GEMM CTAs])  +  (adj bit-pack
//   [8192 CTAs]).  Independent work co-scheduled: pack's DRAM time hides
//   under GEMM's FMA time.  GEMM epilogue also emits fp16 h^T.
// ============================================================
#define G1_BM 128
#define G1_BN 128
#define G1_BK 16
#define GEMM_BLOCKS 128                 // 64 rowtiles x 2 coltiles

__global__ __launch_bounds__(256) void gp_kernel(
    const float* __restrict__ A, const float* __restrict__ B,
    const int* __restrict__ adj,
    float* __restrict__ C, __half* __restrict__ CT,
    uint32_t* __restrict__ mask)
{
    if (blockIdx.x >= GEMM_BLOCKS) {
        // ---------------- pack role ----------------
        const int row = blockIdx.x - GEMM_BLOCKS;
        const int wid = threadIdx.x >> 5, lane = threadIdx.x & 31;
        const int* ar = adj + (size_t)row * NN;
#pragma unroll 4
        for (int i = 0; i < 32; i++) {
            int t = wid * 32 + i;
            int v = ar[t * 32 + lane];
            uint32_t b = __ballot_sync(0xffffffffu, v > 0);
            if (lane == 0) mask[row * 256 + t] = b;
        }
        return;
    }

    // ---------------- GEMM role ----------------
    __shared__ float As[G1_BK][G1_BM + 4];
    __shared__ float Bs[G1_BK][G1_BN + 4];

    const int row0 = (blockIdx.x >> 1) * G1_BM;
    const int col0 = (blockIdx.x & 1) * G1_BN;
    const int tid = threadIdx.x;
    const int tx = tid & 15, ty = tid >> 4;

    unsigned long long acc2[8][4];
#pragma unroll
    for (int i = 0; i < 8; i++)
#pragma unroll
        for (int j = 0; j < 4; j++) acc2[i][j] = 0ULL;

    for (int k0 = 0; k0 < FIN; k0 += G1_BK) {
#pragma unroll
        for (int it = 0; it < 2; it++) {
            int i = tid + it * 256;
            int r = i >> 2, c4 = i & 3;
            float4 v = *(const float4*)&A[(row0 + r) * FIN + k0 + c4 * 4];
            As[c4 * 4 + 0][r] = v.x;
            As[c4 * 4 + 1][r] = v.y;
            As[c4 * 4 + 2][r] = v.z;
            As[c4 * 4 + 3][r] = v.w;
        }
#pragma unroll
        for (int it = 0; it < 2; it++) {
            int i = tid + it * 256;
            int r = i >> 5, c4 = i & 31;
            float4 v = *(const float4*)&B[(k0 + r) * FOUT + col0 + c4 * 4];
            *(float4*)&Bs[r][c4 * 4] = v;
        }
        __syncthreads();

#pragma unroll
        for (int k = 0; k < G1_BK; k++) {
            float4 a0 = *(const float4*)&As[k][ty * 8];
            float4 a1 = *(const float4*)&As[k][ty * 8 + 4];
            float af[8] = {a0.x, a0.y, a0.z, a0.w, a1.x, a1.y, a1.z, a1.w};
            ulonglong2 b01 = ((const ulonglong2*)&Bs[k][tx * 8])[0];
            ulonglong2 b23 = ((const ulonglong2*)&Bs[k][tx * 8])[1];
            unsigned long long bb[4] = {b01.x, b01.y, b23.x, b23.y};
#pragma unroll
            for (int i = 0; i < 8; i++) {
                unsigned long long pa = pack2(af[i], af[i]);
#pragma unroll
                for (int j = 0; j < 4; j++)
                    asm("fma.rn.f32x2 %0, %1, %2, %0;"
                        : "+l"(acc2[i][j]) : "l"(pa), "l"(bb[j]));
            }
        }
        __syncthreads();
    }

    // epilogue: fp32 h + fp16 h^T
    float vv[8][8];
#pragma unroll
    for (int i = 0; i < 8; i++) {
#pragma unroll
        for (int j2 = 0; j2 < 4; j2++)
            unpack2(acc2[i][j2], vv[i][j2 * 2], vv[i][j2 * 2 + 1]);
        int r = row0 + ty * 8 + i;
        *(float4*)&C[r * FOUT + col0 + tx * 8]     = make_float4(vv[i][0], vv[i][1], vv[i][2], vv[i][3]);
        *(float4*)&C[r * FOUT + col0 + tx * 8 + 4] = make_float4(vv[i][4], vv[i][5], vv[i][6], vv[i][7]);
    }
#pragma unroll
    for (int j = 0; j < 8; j++) {
        int c = col0 + tx * 8 + j;
        __half hx[8];
#pragma unroll
        for (int i = 0; i < 8; i++) hx[i] = __float2half(vv[i][j]);
        *(uint4*)&CT[(size_t)c * NN + row0 + ty * 8] = *(uint4*)hx;
    }
}

// ============================================================
// Kernel 2: s1/s2 dot products (raw)
// ============================================================
__global__ __launch_bounds__(256) void s_kernel(
    const float* __restrict__ h, const float* __restrict__ a)
{
    int row = blockIdx.x * 8 + (threadIdx.x >> 5);
    int lane = threadIdx.x & 31;
    float a1 = 0.f, a2 = 0.f;
#pragma unroll
    for (int c = lane; c < FOUT; c += 32) {
        float hv = h[row * FOUT + c];
        a1 = fmaf(hv, a[c], a1);
        a2 = fmaf(hv, a[FOUT + c], a2);
    }
#pragma unroll
    for (int o = 16; o; o >>= 1) {
        a1 += __shfl_xor_sync(0xffffffffu, a1, o);
        a2 += __shfl_xor_sync(0xffffffffu, a2, o);
    }
    if (lane == 0) { g_s1r[row] = a1; g_s2r[row] = a2; }
}

// ============================================================
// Kernel 2b: S2MAX reduction + factor tables (1 block)
// ============================================================
__global__ __launch_bounds__(256) void prep_kernel(void)
{
    __shared__ float red[256];
    float mx = -3.0e38f;
    for (int i = threadIdx.x; i < NN; i += 256) mx = fmaxf(mx, g_s2r[i]);
    red[threadIdx.x] = mx;
    __syncthreads();
#pragma unroll
    for (int s = 128; s; s >>= 1) {
        if (threadIdx.x < s) red[threadIdx.x] = fmaxf(red[threadIdx.x], red[threadIdx.x + s]);
        __syncthreads();
    }
    const float S2MAX = red[0];
    for (int r = threadIdx.x; r < NN; r += 256) {
        float s1 = g_s1r[r], s2 = g_s2r[r];
        float x = s1 + S2MAX;
        float m = fmaxf(x, 0.2f * x);
        g_e1[r] = make_float2(expf(s1 - m), expf(0.2f * s1 - m));
        g_e2[r] = make_float2(expf(s2), expf(0.2f * s2));
    }
}

// ============================================================
// Kernel 3: fused attention GEMM, mma.sync fp16 m16n8k16.
//   R8 shape: 256 thr / 8 warps x 32 rows x 17 nb, grid 128.
//   New: 3-stage cp.async pipeline + mask prefetch distance 2.
// ============================================================
#define AT_THREADS 256
#define KT 32
#define ATILES 128
#define HSTRH 40                         // halves per Hs row
#define HS_BYTES (136 * HSTRH * 2)       // 10880
#define OFF_E2  (3 * HS_BYTES)           // 32640
#define AT_SMEM (OFF_E2 + 4096 * 8)      // 65408

__global__ void __launch_bounds__(AT_THREADS, 1) attn_kernel(void)
{
    extern __shared__ char dsm[];
    __half* HsB[3] = { (__half*)dsm, (__half*)(dsm + HS_BYTES), (__half*)(dsm + 2 * HS_BYTES) };
    float2* e2sm = (float2*)(dsm + OFF_E2);

    const int tid = threadIdx.x, wid = tid >> 5, lane = tid & 31;
    const int q = lane >> 2, tc = lane & 3;
    const int rt = blockIdx.x >> 2, kh = (blockIdx.x >> 1) & 1, nh = blockIdx.x & 1;
    const int row0 = rt * 256, kbase = kh * 4096, nbase = nh * 128;

    // ---- stage e2 table (32 KB), group 0 ----
    {
        uint32_t dst = smem_u32(e2sm) + (uint32_t)tid * 16u;
        const float4* src = (const float4*)(g_e2 + kbase) + tid;
#pragma unroll
        for (int it = 0; it < 8; it++)
            asm volatile("cp.async.cg.shared.global [%0], [%1], 16;"
                         :: "r"(dst + it * 4096u), "l"(src + it * 256));
        asm volatile("cp.async.commit_group;");
    }
    // ---- ones rows (n local 128..135), all 3 buffers ----
    for (int i = tid; i < 8 * HSTRH / 2; i += AT_THREADS) {
        int r = 128 + i / (HSTRH / 2), c = i % (HSTRH / 2);
        ((uint32_t*)HsB[0])[(r * HSTRH) / 2 + c] = 0x3C003C00u;
        ((uint32_t*)HsB[1])[(r * HSTRH) / 2 + c] = 0x3C003C00u;
        ((uint32_t*)HsB[2])[(r * HSTRH) / 2 + c] = 0x3C003C00u;
    }
    // ---- prefetch H tiles 0 and 1 (groups 1, 2) ----
#pragma unroll
    for (int pt = 0; pt < 2; pt++) {
        uint32_t dstb = smem_u32(HsB[pt]);
        const __half* src = g_hT + (size_t)nbase * NN + kbase + pt * KT;
#pragma unroll
        for (int it = 0; it < 2; it++) {
            int i = tid + it * AT_THREADS;
            int n = i >> 2, c16 = i & 3;
            asm volatile("cp.async.cg.shared.global [%0], [%1], 16;"
                         :: "r"(dstb + (uint32_t)(n * HSTRH * 2 + c16 * 16)),
                            "l"(src + (size_t)n * NN + c16 * 8));
        }
        asm volatile("cp.async.commit_group;");
    }

    // ---- per-row constants (rows q + {0,8,16,24} of warp's 32) ----
    float f1p[4], f1n[4];
    const uint32_t* mrow[4];
#pragma unroll
    for (int r = 0; r < 4; r++) {
        int grow = row0 + wid * 32 + q + r * 8;
        float2 e = g_e1[grow];
        f1p[r] = e.x; f1n[r] = e.y;
        mrow[r] = g_mask + (size_t)grow * 256 + kh * 128;
    }
    uint32_t m0[4], m1[4];
#pragma unroll
    for (int r = 0; r < 4; r++) { m0[r] = mrow[r][0]; m1[r] = mrow[r][1]; }

    float acc[2][17][4];
#pragma unroll
    for (int g = 0; g < 2; g++)
#pragma unroll
        for (int nb = 0; nb < 17; nb++)
#pragma unroll
            for (int j = 0; j < 4; j++) acc[g][nb][j] = 0.f;

    for (int t = 0; t < ATILES; t++) {
        // mask prefetch, distance 2
        uint32_t m2[4] = {0, 0, 0, 0};
        if (t + 2 < ATILES) {
#pragma unroll
            for (int r = 0; r < 4; r++) m2[r] = mrow[r][t + 2];
        }
        // H prefetch, distance 2 (3-stage)
        if (t + 2 < ATILES) {
            uint32_t dstb = smem_u32(HsB[(t + 2) % 3]);
            const __half* src = g_hT + (size_t)nbase * NN + kbase + (t + 2) * KT;
#pragma unroll
            for (int it = 0; it < 2; it++) {
                int i = tid + it * AT_THREADS;
                int n = i >> 2, c16 = i & 3;
                asm volatile("cp.async.cg.shared.global [%0], [%1], 16;"
                             :: "r"(dstb + (uint32_t)(n * HSTRH * 2 + c16 * 16)),
                                "l"(src + (size_t)n * NN + c16 * 8));
            }
            asm volatile("cp.async.commit_group;");
            asm volatile("cp.async.wait_group 2;");
        } else {
            asm volatile("cp.async.wait_group 0;");
        }
        __syncthreads();

        const __half* Hb = HsB[t % 3];
        const int kl0 = t * KT;

#pragma unroll
        for (int c = 0; c < 2; c++) {           // two k16 chunks
            const int kc = c * 16 + 2 * tc;
            float2 e0 = e2sm[kl0 + kc];
            float2 e1 = e2sm[kl0 + kc + 1];
            float2 e8 = e2sm[kl0 + kc + 8];
            float2 e9 = e2sm[kl0 + kc + 9];
            const uint32_t b0m = 1u << kc, b1m = 2u << kc;
            const uint32_t b8m = 256u << kc, b9m = 512u << kc;

            uint32_t af[2][4];
#pragma unroll
            for (int r = 0; r < 4; r++) {
                float p0 = fmaxf(f1p[r] * e0.x, f1n[r] * e0.y);
                float p1 = fmaxf(f1p[r] * e1.x, f1n[r] * e1.y);
                float p8 = fmaxf(f1p[r] * e8.x, f1n[r] * e8.y);
                float p9 = fmaxf(f1p[r] * e9.x, f1n[r] * e9.y);
                p0 = (m0[r] & b0m) ? p0 : 0.f;
                p1 = (m0[r] & b1m) ? p1 : 0.f;
                p8 = (m0[r] & b8m) ? p8 : 0.f;
                p9 = (m0[r] & b9m) ? p9 : 0.f;
                af[r >> 1][(r & 1)]     = f16x2_pack(p1, p0);
                af[r >> 1][(r & 1) + 2] = f16x2_pack(p9, p8);
            }

            const __half* bp = Hb + q * HSTRH + c * 16 + 2 * tc;
#pragma unroll
            for (int nb = 0; nb < 17; nb++) {
                uint32_t b0 = *(const uint32_t*)(bp + nb * 8 * HSTRH);
                uint32_t b1 = *(const uint32_t*)(bp + nb * 8 * HSTRH + 8);
                asm volatile(
                    "mma.sync.aligned.m16n8k16.row.col.f32.f16.f16.f32 "
                    "{%0,%1,%2,%3}, {%4,%5,%6,%7}, {%8,%9}, {%0,%1,%2,%3};"
                    : "+f"(acc[0][nb][0]), "+f"(acc[0][nb][1]),
                      "+f"(acc[0][nb][2]), "+f"(acc[0][nb][3])
                    : "r"(af[0][0]), "r"(af[0][1]), "r"(af[0][2]), "r"(af[0][3]),
                      "r"(b0), "r"(b1));
                asm volatile(
                    "mma.sync.aligned.m16n8k16.row.col.f32.f16.f16.f32 "
                    "{%0,%1,%2,%3}, {%4,%5,%6,%7}, {%8,%9}, {%0,%1,%2,%3};"
                    : "+f"(acc[1][nb][0]), "+f"(acc[1][nb][1]),
                      "+f"(acc[1][nb][2]), "+f"(acc[1][nb][3])
                    : "r"(af[1][0]), "r"(af[1][1]), "r"(af[1][2]), "r"(af[1][3]),
                      "r"(b0), "r"(b1));
            }
        }
        __syncthreads();

#pragma unroll
        for (int r = 0; r < 4; r++) { m0[r] = m1[r]; m1[r] = m2[r]; }
    }

    // ---- store partial D + z ----
    float* dp = g_dpart + (size_t)kh * NN * FOUT;
#pragma unroll
    for (int g = 0; g < 2; g++) {
        const int rlo = row0 + wid * 32 + g * 16 + q;
        const int rhi = rlo + 8;
#pragma unroll
        for (int nb = 0; nb < 16; nb++) {
            int c = nbase + nb * 8 + tc * 2;
            *(float2*)&dp[(size_t)rlo * FOUT + c] = make_float2(acc[g][nb][0], acc[g][nb][1]);
            *(float2*)&dp[(size_t)rhi * FOUT + c] = make_float2(acc[g][nb][2], acc[g][nb][3]);
        }
        if (nh == 0 && tc == 0) {
            g_z[kh * NN + rlo] = acc[g][16][0];
            g_z[kh * NN + rhi] = acc[g][16][2];
        }
    }
}

// ============================================================
// Kernel 4: combine K-split partials, normalize, ELU
// ============================================================
__global__ __launch_bounds__(256) void combine_kernel(float* __restrict__ out)
{
    int idx = blockIdx.x * 256 + threadIdx.x;
    const float4* d0 = (const float4*)g_dpart;
    const float4* d1 = d0 + (NN * FOUT / 4);
    float4 a = d0[idx], b = d1[idx];
    int row = idx >> 6;
    float inv = 1.0f / (g_z[row] + g_z[NN + row]);
    float4 o; float t;
    t = (a.x + b.x) * inv; o.x = (t > 0.f) ? t : expm1f(t);
    t = (a.y + b.y) * inv; o.y = (t > 0.f) ? t : expm1f(t);
    t = (a.z + b.z) * inv; o.z = (t > 0.f) ? t : expm1f(t);
    t = (a.w + b.w) * inv; o.w = (t > 0.f) ? t : expm1f(t);
    ((float4*)out)[idx] = o;
}

// ============================================================
// launch
// ============================================================
extern "C" void kernel_launch(void* const* d_in, const int* in_sizes, int n_in,
                              void* d_out, int out_size)
{
    const float* input = (const float*)d_in[0];   // [8192, 512]
    const int*   adj   = (const int*)  d_in[1];   // [8192, 8192]
    const float* W     = (const float*)d_in[2];   // [512, 256]
    const float* a     = (const float*)d_in[3];   // [512, 1]
    float* out = (float*)d_out;                   // [8192, 256]

    float* h;
    __half* hT;
    uint32_t* mask;
    cudaGetSymbolAddress((void**)&h, g_h);
    cudaGetSymbolAddress((void**)&hT, g_hT);
    cudaGetSymbolAddress((void**)&mask, g_mask);

    cudaFuncSetAttribute(attn_kernel, cudaFuncAttributeMaxDynamicSharedMemorySize, AT_SMEM);

    gp_kernel<<<GEMM_BLOCKS + NN, 256>>>(input, W, adj, h, hT, mask);
    s_kernel<<<NN / 8, 256>>>(h, a);
    prep_kernel<<<1, 256>>>();
    attn_kernel<<<128, AT_THREADS, AT_SMEM>>>();
    combine_kernel<<<NN * FOUT / 4 / 256, 256>>>(out);
}

// round 13
// speedup vs baseline: 1.1903x; 1.1903x over previous
#include <cuda_runtime.h>
#include <cuda_fp16.h>
#include <cstdint>

#define NN   8192
#define FIN  512
#define FOUT 256

// ---- scratch (static device memory; no allocation) ----
__device__ __align__(16) float g_h [NN * FOUT];          // fp32 h
__device__ __align__(16) __half g_hT[FOUT * NN];         // fp16 h transposed [n][j]
__device__ __align__(16) float g_s1r[NN];
__device__ __align__(16) float g_s2r[NN];
__device__ __align__(16) float2 g_e1[NN];                // (exp(s1-m), exp(.2 s1-m))
__device__ __align__(16) float2 g_e2[NN];                // (exp(s2), exp(.2 s2))
__device__ __align__(16) uint32_t g_mask[NN * 256];      // bit-packed adj
__device__ __align__(16) float g_dpart[2 * NN * FOUT];
__device__ __align__(16) float g_z[2 * NN];

// ============================================================
// helpers
// ============================================================
__device__ __forceinline__ uint32_t smem_u32(const void* p) {
    uint32_t a;
    asm("{ .reg .u64 t; cvta.to.shared.u64 t, %1; cvt.u32.u64 %0, t; }" : "=r"(a) : "l"(p));
    return a;
}
__device__ __forceinline__ unsigned long long pack2(float lo, float hi) {
    unsigned long long r;
    asm("mov.b64 %0, {%1, %2};" : "=l"(r) : "f"(lo), "f"(hi));
    return r;
}
__device__ __forceinline__ void unpack2(unsigned long long v, float& lo, float& hi) {
    asm("mov.b64 {%0, %1}, %2;" : "=f"(lo), "=f"(hi) : "l"(v));
}
__device__ __forceinline__ uint32_t f16x2_pack(float hi, float lo) {
    uint32_t r;
    asm("cvt.rn.f16x2.f32 %0, %1, %2;" : "=r"(r) : "f"(hi), "f"(lo));
    return r;
}

// ============================================================
// Kernel 0: bit-pack adjacency (own kernel: low regs, high occupancy,
//   DRAM-bound at ~33 us floor)
// ============================================================
__global__ __launch_bounds__(256) void pack_kernel(const int* __restrict__ adj,
                                                   uint32_t* __restrict__ mask)
{
    const int row = blockIdx.x;
    const int wid = threadIdx.x >> 5, lane = threadIdx.x & 31;
    const int* ar = adj + (size_t)row * NN;
#pragma unroll 4
    for (int i = 0; i < 32; i++) {
        int t = wid * 32 + i;
        int v = ar[t * 32 + lane];
        uint32_t b = __ballot_sync(0xffffffffu, v > 0);
        if (lane == 0) mask[row * 256 + t] = b;
    }
}

// ============================================================
// Kernel 1: h = input @ W (fp32, packed fma.rn.f32x2).
//   Epilogue emits fp32 h AND fp16 h^T (no separate transpose pass).
// ============================================================
#define G1_BM 128
#define G1_BN 128
#define G1_BK 16

__global__ __launch_bounds__(256) void gemm_h_kernel(
    const float* __restrict__ A, const float* __restrict__ B,
    float* __restrict__ C, __half* __restrict__ CT)
{
    __shared__ float As[G1_BK][G1_BM + 4];
    __shared__ float Bs[G1_BK][G1_BN + 4];

    const int row0 = blockIdx.x * G1_BM;
    const int col0 = blockIdx.y * G1_BN;
    const int tid = threadIdx.x;
    const int tx = tid & 15, ty = tid >> 4;

    unsigned long long acc2[8][4];
#pragma unroll
    for (int i = 0; i < 8; i++)
#pragma unroll
        for (int j = 0; j < 4; j++) acc2[i][j] = 0ULL;

    for (int k0 = 0; k0 < FIN; k0 += G1_BK) {
#pragma unroll
        for (int it = 0; it < 2; it++) {
            int i = tid + it * 256;
            int r = i >> 2, c4 = i & 3;
            float4 v = *(const float4*)&A[(row0 + r) * FIN + k0 + c4 * 4];
            As[c4 * 4 + 0][r] = v.x;
            As[c4 * 4 + 1][r] = v.y;
            As[c4 * 4 + 2][r] = v.z;
            As[c4 * 4 + 3][r] = v.w;
        }
#pragma unroll
        for (int it = 0; it < 2; it++) {
            int i = tid + it * 256;
            int r = i >> 5, c4 = i & 31;
            float4 v = *(const float4*)&B[(k0 + r) * FOUT + col0 + c4 * 4];
            *(float4*)&Bs[r][c4 * 4] = v;
        }
        __syncthreads();

#pragma unroll
        for (int k = 0; k < G1_BK; k++) {
            float4 a0 = *(const float4*)&As[k][ty * 8];
            float4 a1 = *(const float4*)&As[k][ty * 8 + 4];
            float af[8] = {a0.x, a0.y, a0.z, a0.w, a1.x, a1.y, a1.z, a1.w};
            ulonglong2 b01 = ((const ulonglong2*)&Bs[k][tx * 8])[0];
            ulonglong2 b23 = ((const ulonglong2*)&Bs[k][tx * 8])[1];
            unsigned long long bb[4] = {b01.x, b01.y, b23.x, b23.y};
#pragma unroll
            for (int i = 0; i < 8; i++) {
                unsigned long long pa = pack2(af[i], af[i]);
#pragma unroll
                for (int j = 0; j < 4; j++)
                    asm("fma.rn.f32x2 %0, %1, %2, %0;"
                        : "+l"(acc2[i][j]) : "l"(pa), "l"(bb[j]));
            }
        }
        __syncthreads();
    }

    // epilogue: fp32 h + fp16 h^T
    float vv[8][8];
#pragma unroll
    for (int i = 0; i < 8; i++) {
#pragma unroll
        for (int j2 = 0; j2 < 4; j2++)
            unpack2(acc2[i][j2], vv[i][j2 * 2], vv[i][j2 * 2 + 1]);
        int r = row0 + ty * 8 + i;
        *(float4*)&C[r * FOUT + col0 + tx * 8]     = make_float4(vv[i][0], vv[i][1], vv[i][2], vv[i][3]);
        *(float4*)&C[r * FOUT + col0 + tx * 8 + 4] = make_float4(vv[i][4], vv[i][5], vv[i][6], vv[i][7]);
    }
#pragma unroll
    for (int j = 0; j < 8; j++) {
        int c = col0 + tx * 8 + j;
        __half hx[8];
#pragma unroll
        for (int i = 0; i < 8; i++) hx[i] = __float2half(vv[i][j]);
        *(uint4*)&CT[(size_t)c * NN + row0 + ty * 8] = *(uint4*)hx;
    }
}

// ============================================================
// Kernel 2: s1/s2 dot products (raw)
// ============================================================
__global__ __launch_bounds__(256) void s_kernel(
    const float* __restrict__ h, const float* __restrict__ a)
{
    int row = blockIdx.x * 8 + (threadIdx.x >> 5);
    int lane = threadIdx.x & 31;
    float a1 = 0.f, a2 = 0.f;
#pragma unroll
    for (int c = lane; c < FOUT; c += 32) {
        float hv = h[row * FOUT + c];
        a1 = fmaf(hv, a[c], a1);
        a2 = fmaf(hv, a[FOUT + c], a2);
    }
#pragma unroll
    for (int o = 16; o; o >>= 1) {
        a1 += __shfl_xor_sync(0xffffffffu, a1, o);
        a2 += __shfl_xor_sync(0xffffffffu, a2, o);
    }
    if (lane == 0) { g_s1r[row] = a1; g_s2r[row] = a2; }
}

// ============================================================
// Kernel 2b: S2MAX reduction + factor tables (1 block)
// ============================================================
__global__ __launch_bounds__(256) void prep_kernel(void)
{
    __shared__ float red[256];
    float mx = -3.0e38f;
    for (int i = threadIdx.x; i < NN; i += 256) mx = fmaxf(mx, g_s2r[i]);
    red[threadIdx.x] = mx;
    __syncthreads();
#pragma unroll
    for (int s = 128; s; s >>= 1) {
        if (threadIdx.x < s) red[threadIdx.x] = fmaxf(red[threadIdx.x], red[threadIdx.x + s]);
        __syncthreads();
    }
    const float S2MAX = red[0];
    for (int r = threadIdx.x; r < NN; r += 256) {
        float s1 = g_s1r[r], s2 = g_s2r[r];
        float x = s1 + S2MAX;
        float m = fmaxf(x, 0.2f * x);
        g_e1[r] = make_float2(expf(s1 - m), expf(0.2f * s1 - m));
        g_e2[r] = make_float2(expf(s2), expf(0.2f * s2));
    }
}

// ============================================================
// Kernel 3: fused attention GEMM, mma.sync fp16 m16n8k16.
//   8 warps x 32 rows x 17 nb, grid 128.
//   3-stage cp.async pipeline + mask prefetch distance 2 (R12 version).
// ============================================================
#define AT_THREADS 256
#define KT 32
#define ATILES 128
#define HSTRH 40                         // halves per Hs row
#define HS_BYTES (136 * HSTRH * 2)       // 10880
#define OFF_E2  (3 * HS_BYTES)           // 32640
#define AT_SMEM (OFF_E2 + 4096 * 8)      // 65408

__global__ void __launch_bounds__(AT_THREADS, 1) attn_kernel(void)
{
    extern __shared__ char dsm[];
    __half* HsB[3] = { (__half*)dsm, (__half*)(dsm + HS_BYTES), (__half*)(dsm + 2 * HS_BYTES) };
    float2* e2sm = (float2*)(dsm + OFF_E2);

    const int tid = threadIdx.x, wid = tid >> 5, lane = tid & 31;
    const int q = lane >> 2, tc = lane & 3;
    const int rt = blockIdx.x >> 2, kh = (blockIdx.x >> 1) & 1, nh = blockIdx.x & 1;
    const int row0 = rt * 256, kbase = kh * 4096, nbase = nh * 128;

    // ---- stage e2 table (32 KB), group 0 ----
    {
        uint32_t dst = smem_u32(e2sm) + (uint32_t)tid * 16u;
        const float4* src = (const float4*)(g_e2 + kbase) + tid;
#pragma unroll
        for (int it = 0; it < 8; it++)
            asm volatile("cp.async.cg.shared.global [%0], [%1], 16;"
                         :: "r"(dst + it * 4096u), "l"(src + it * 256));
        asm volatile("cp.async.commit_group;");
    }
    // ---- ones rows (n local 128..135), all 3 buffers ----
    for (int i = tid; i < 8 * HSTRH / 2; i += AT_THREADS) {
        int r = 128 + i / (HSTRH / 2), c = i % (HSTRH / 2);
        ((uint32_t*)HsB[0])[(r * HSTRH) / 2 + c] = 0x3C003C00u;
        ((uint32_t*)HsB[1])[(r * HSTRH) / 2 + c] = 0x3C003C00u;
        ((uint32_t*)HsB[2])[(r * HSTRH) / 2 + c] = 0x3C003C00u;
    }
    // ---- prefetch H tiles 0 and 1 (groups 1, 2) ----
#pragma unroll
    for (int pt = 0; pt < 2; pt++) {
        uint32_t dstb = smem_u32(HsB[pt]);
        const __half* src = g_hT + (size_t)nbase * NN + kbase + pt * KT;
#pragma unroll
        for (int it = 0; it < 2; it++) {
            int i = tid + it * AT_THREADS;
            int n = i >> 2, c16 = i & 3;
            asm volatile("cp.async.cg.shared.global [%0], [%1], 16;"
                         :: "r"(dstb + (uint32_t)(n * HSTRH * 2 + c16 * 16)),
                            "l"(src + (size_t)n * NN + c16 * 8));
        }
        asm volatile("cp.async.commit_group;");
    }

    // ---- per-row constants (rows q + {0,8,16,24} of warp's 32) ----
    float f1p[4], f1n[4];
    const uint32_t* mrow[4];
#pragma unroll
    for (int r = 0; r < 4; r++) {
        int grow = row0 + wid * 32 + q + r * 8;
        float2 e = g_e1[grow];
        f1p[r] = e.x; f1n[r] = e.y;
        mrow[r] = g_mask + (size_t)grow * 256 + kh * 128;
    }
    uint32_t m0[4], m1[4];
#pragma unroll
    for (int r = 0; r < 4; r++) { m0[r] = mrow[r][0]; m1[r] = mrow[r][1]; }

    float acc[2][17][4];
#pragma unroll
    for (int g = 0; g < 2; g++)
#pragma unroll
        for (int nb = 0; nb < 17; nb++)
#pragma unroll
            for (int j = 0; j < 4; j++) acc[g][nb][j] = 0.f;

    for (int t = 0; t < ATILES; t++) {
        // mask prefetch, distance 2
        uint32_t m2[4] = {0, 0, 0, 0};
        if (t + 2 < ATILES) {
#pragma unroll
            for (int r = 0; r < 4; r++) m2[r] = mrow[r][t + 2];
        }
        // H prefetch, distance 2 (3-stage)
        if (t + 2 < ATILES) {
            uint32_t dstb = smem_u32(HsB[(t + 2) % 3]);
            const __half* src = g_hT + (size_t)nbase * NN + kbase + (t + 2) * KT;
#pragma unroll
            for (int it = 0; it < 2; it++) {
                int i = tid + it * AT_THREADS;
                int n = i >> 2, c16 = i & 3;
                asm volatile("cp.async.cg.shared.global [%0], [%1], 16;"
                             :: "r"(dstb + (uint32_t)(n * HSTRH * 2 + c16 * 16)),
                                "l"(src + (size_t)n * NN + c16 * 8));
            }
            asm volatile("cp.async.commit_group;");
            asm volatile("cp.async.wait_group 2;");
        } else {
            asm volatile("cp.async.wait_group 0;");
        }
        __syncthreads();

        const __half* Hb = HsB[t % 3];
        const int kl0 = t * KT;

#pragma unroll
        for (int c = 0; c < 2; c++) {           // two k16 chunks
            const int kc = c * 16 + 2 * tc;
            float2 e0 = e2sm[kl0 + kc];
            float2 e1 = e2sm[kl0 + kc + 1];
            float2 e8 = e2sm[kl0 + kc + 8];
            float2 e9 = e2sm[kl0 + kc + 9];
            const uint32_t b0m = 1u << kc, b1m = 2u << kc;
            const uint32_t b8m = 256u << kc, b9m = 512u << kc;

            uint32_t af[2][4];
#pragma unroll
            for (int r = 0; r < 4; r++) {
                float p0 = fmaxf(f1p[r] * e0.x, f1n[r] * e0.y);
                float p1 = fmaxf(f1p[r] * e1.x, f1n[r] * e1.y);
                float p8 = fmaxf(f1p[r] * e8.x, f1n[r] * e8.y);
                float p9 = fmaxf(f1p[r] * e9.x, f1n[r] * e9.y);
                p0 = (m0[r] & b0m) ? p0 : 0.f;
                p1 = (m0[r] & b1m) ? p1 : 0.f;
                p8 = (m0[r] & b8m) ? p8 : 0.f;
                p9 = (m0[r] & b9m) ? p9 : 0.f;
                af[r >> 1][(r & 1)]     = f16x2_pack(p1, p0);
                af[r >> 1][(r & 1) + 2] = f16x2_pack(p9, p8);
            }

            const __half* bp = Hb + q * HSTRH + c * 16 + 2 * tc;
#pragma unroll
            for (int nb = 0; nb < 17; nb++) {
                uint32_t b0 = *(const uint32_t*)(bp + nb * 8 * HSTRH);
                uint32_t b1 = *(const uint32_t*)(bp + nb * 8 * HSTRH + 8);
                asm volatile(
                    "mma.sync.aligned.m16n8k16.row.col.f32.f16.f16.f32 "
                    "{%0,%1,%2,%3}, {%4,%5,%6,%7}, {%8,%9}, {%0,%1,%2,%3};"
                    : "+f"(acc[0][nb][0]), "+f"(acc[0][nb][1]),
                      "+f"(acc[0][nb][2]), "+f"(acc[0][nb][3])
                    : "r"(af[0][0]), "r"(af[0][1]), "r"(af[0][2]), "r"(af[0][3]),
                      "r"(b0), "r"(b1));
                asm volatile(
                    "mma.sync.aligned.m16n8k16.row.col.f32.f16.f16.f32 "
                    "{%0,%1,%2,%3}, {%4,%5,%6,%7}, {%8,%9}, {%0,%1,%2,%3};"
                    : "+f"(acc[1][nb][0]), "+f"(acc[1][nb][1]),
                      "+f"(acc[1][nb][2]), "+f"(acc[1][nb][3])
                    : "r"(af[1][0]), "r"(af[1][1]), "r"(af[1][2]), "r"(af[1][3]),
                      "r"(b0), "r"(b1));
            }
        }
        __syncthreads();

#pragma unroll
        for (int r = 0; r < 4; r++) { m0[r] = m1[r]; m1[r] = m2[r]; }
    }

    // ---- store partial D + z ----
    float* dp = g_dpart + (size_t)kh * NN * FOUT;
#pragma unroll
    for (int g = 0; g < 2; g++) {
        const int rlo = row0 + wid * 32 + g * 16 + q;
        const int rhi = rlo + 8;
#pragma unroll
        for (int nb = 0; nb < 16; nb++) {
            int c = nbase + nb * 8 + tc * 2;
            *(float2*)&dp[(size_t)rlo * FOUT + c] = make_float2(acc[g][nb][0], acc[g][nb][1]);
            *(float2*)&dp[(size_t)rhi * FOUT + c] = make_float2(acc[g][nb][2], acc[g][nb][3]);
        }
        if (nh == 0 && tc == 0) {
            g_z[kh * NN + rlo] = acc[g][16][0];
            g_z[kh * NN + rhi] = acc[g][16][2];
        }
    }
}

// ============================================================
// Kernel 4: combine K-split partials, normalize, ELU
// ============================================================
__global__ __launch_bounds__(256) void combine_kernel(float* __restrict__ out)
{
    int idx = blockIdx.x * 256 + threadIdx.x;
    const float4* d0 = (const float4*)g_dpart;
    const float4* d1 = d0 + (NN * FOUT / 4);
    float4 a = d0[idx], b = d1[idx];
    int row = idx >> 6;
    float inv = 1.0f / (g_z[row] + g_z[NN + row]);
    float4 o; float t;
    t = (a.x + b.x) * inv; o.x = (t > 0.f) ? t : expm1f(t);
    t = (a.y + b.y) * inv; o.y = (t > 0.f) ? t : expm1f(t);
    t = (a.z + b.z) * inv; o.z = (t > 0.f) ? t : expm1f(t);
    t = (a.w + b.w) * inv; o.w = (t > 0.f) ? t : expm1f(t);
    ((float4*)out)[idx] = o;
}

// ============================================================
// launch
// ============================================================
extern "C" void kernel_launch(void* const* d_in, const int* in_sizes, int n_in,
                              void* d_out, int out_size)
{
    const float* input = (const float*)d_in[0];   // [8192, 512]
    const int*   adj   = (const int*)  d_in[1];   // [8192, 8192]
    const float* W     = (const float*)d_in[2];   // [512, 256]
    const float* a     = (const float*)d_in[3];   // [512, 1]
    float* out = (float*)d_out;                   // [8192, 256]

    float* h;
    __half* hT;
    uint32_t* mask;
    cudaGetSymbolAddress((void**)&h, g_h);
    cudaGetSymbolAddress((void**)&hT, g_hT);
    cudaGetSymbolAddress((void**)&mask, g_mask);

    cudaFuncSetAttribute(attn_kernel, cudaFuncAttributeMaxDynamicSharedMemorySize, AT_SMEM);

    pack_kernel<<<NN, 256>>>(adj, mask);
    gemm_h_kernel<<<dim3(NN / G1_BM, FOUT / G1_BN), 256>>>(input, W, h, hT);
    s_kernel<<<NN / 8, 256>>>(h, a);
    prep_kernel<<<1, 256>>>();
    attn_kernel<<<128, AT_THREADS, AT_SMEM>>>();
    combine_kernel<<<NN * FOUT / 4 / 256, 256>>>(out);
}

// round 14
// speedup vs baseline: 1.2937x; 1.0869x over previous
#include <cuda_runtime.h>
#include <cuda_fp16.h>
#include <cstdint>

#define NN   8192
#define FIN  512
#define FOUT 256

// ---- scratch (static device memory; no allocation) ----
__device__ __align__(16) float g_h [NN * FOUT];          // fp32 h
__device__ __align__(16) __half g_hT[FOUT * NN];         // fp16 h transposed [n][j]
__device__ __align__(16) float g_s1r[NN];
__device__ __align__(16) float g_s2r[NN];
__device__ __align__(16) float g_s2max[1];
__device__ __align__(16) float2 g_e1[NN];                // (exp(s1-m), exp(.2 s1-m))
__device__ __align__(16) float2 g_e2[NN];                // (exp(s2), exp(.2 s2))
__device__ __align__(16) uint32_t g_mask[NN * 256];      // bit-packed adj
__device__ __align__(16) float g_dpart[2 * NN * FOUT];
__device__ __align__(16) float g_z[2 * NN];

// ============================================================
// helpers
// ============================================================
__device__ __forceinline__ uint32_t smem_u32(const void* p) {
    uint32_t a;
    asm("{ .reg .u64 t; cvta.to.shared.u64 t, %1; cvt.u32.u64 %0, t; }" : "=r"(a) : "l"(p));
    return a;
}
__device__ __forceinline__ unsigned long long pack2(float lo, float hi) {
    unsigned long long r;
    asm("mov.b64 %0, {%1, %2};" : "=l"(r) : "f"(lo), "f"(hi));
    return r;
}
__device__ __forceinline__ void unpack2(unsigned long long v, float& lo, float& hi) {
    asm("mov.b64 {%0, %1}, %2;" : "=f"(lo), "=f"(hi) : "l"(v));
}
__device__ __forceinline__ uint32_t f16x2_pack(float hi, float lo) {
    uint32_t r;
    asm("cvt.rn.f16x2.f32 %0, %1, %2;" : "=r"(r) : "f"(hi), "f"(lo));
    return r;
}

// ============================================================
// Kernel 0: bit-pack adjacency (own kernel: DRAM-bound, ~33 us floor)
// ============================================================
__global__ __launch_bounds__(256) void pack_kernel(const int* __restrict__ adj,
                                                   uint32_t* __restrict__ mask)
{
    const int row = blockIdx.x;
    const int wid = threadIdx.x >> 5, lane = threadIdx.x & 31;
    const int* ar = adj + (size_t)row * NN;
#pragma unroll 4
    for (int i = 0; i < 32; i++) {
        int t = wid * 32 + i;
        int v = ar[t * 32 + lane];
        uint32_t b = __ballot_sync(0xffffffffu, v > 0);
        if (lane == 0) mask[row * 256 + t] = b;
    }
}

// ============================================================
// Kernel 1: h = input @ W (fp32, packed fma.rn.f32x2).
//   Epilogue emits fp32 h AND fp16 h^T.
// ============================================================
#define G1_BM 128
#define G1_BN 128
#define G1_BK 16

__global__ __launch_bounds__(256) void gemm_h_kernel(
    const float* __restrict__ A, const float* __restrict__ B,
    float* __restrict__ C, __half* __restrict__ CT)
{
    __shared__ float As[G1_BK][G1_BM + 4];
    __shared__ float Bs[G1_BK][G1_BN + 4];

    const int row0 = blockIdx.x * G1_BM;
    const int col0 = blockIdx.y * G1_BN;
    const int tid = threadIdx.x;
    const int tx = tid & 15, ty = tid >> 4;

    unsigned long long acc2[8][4];
#pragma unroll
    for (int i = 0; i < 8; i++)
#pragma unroll
        for (int j = 0; j < 4; j++) acc2[i][j] = 0ULL;

    for (int k0 = 0; k0 < FIN; k0 += G1_BK) {
#pragma unroll
        for (int it = 0; it < 2; it++) {
            int i = tid + it * 256;
            int r = i >> 2, c4 = i & 3;
            float4 v = *(const float4*)&A[(row0 + r) * FIN + k0 + c4 * 4];
            As[c4 * 4 + 0][r] = v.x;
            As[c4 * 4 + 1][r] = v.y;
            As[c4 * 4 + 2][r] = v.z;
            As[c4 * 4 + 3][r] = v.w;
        }
#pragma unroll
        for (int it = 0; it < 2; it++) {
            int i = tid + it * 256;
            int r = i >> 5, c4 = i & 31;
            float4 v = *(const float4*)&B[(k0 + r) * FOUT + col0 + c4 * 4];
            *(float4*)&Bs[r][c4 * 4] = v;
        }
        __syncthreads();

#pragma unroll
        for (int k = 0; k < G1_BK; k++) {
            float4 a0 = *(const float4*)&As[k][ty * 8];
            float4 a1 = *(const float4*)&As[k][ty * 8 + 4];
            float af[8] = {a0.x, a0.y, a0.z, a0.w, a1.x, a1.y, a1.z, a1.w};
            ulonglong2 b01 = ((const ulonglong2*)&Bs[k][tx * 8])[0];
            ulonglong2 b23 = ((const ulonglong2*)&Bs[k][tx * 8])[1];
            unsigned long long bb[4] = {b01.x, b01.y, b23.x, b23.y};
#pragma unroll
            for (int i = 0; i < 8; i++) {
                unsigned long long pa = pack2(af[i], af[i]);
#pragma unroll
                for (int j = 0; j < 4; j++)
                    asm("fma.rn.f32x2 %0, %1, %2, %0;"
                        : "+l"(acc2[i][j]) : "l"(pa), "l"(bb[j]));
            }
        }
        __syncthreads();
    }

    float vv[8][8];
#pragma unroll
    for (int i = 0; i < 8; i++) {
#pragma unroll
        for (int j2 = 0; j2 < 4; j2++)
            unpack2(acc2[i][j2], vv[i][j2 * 2], vv[i][j2 * 2 + 1]);
        int r = row0 + ty * 8 + i;
        *(float4*)&C[r * FOUT + col0 + tx * 8]     = make_float4(vv[i][0], vv[i][1], vv[i][2], vv[i][3]);
        *(float4*)&C[r * FOUT + col0 + tx * 8 + 4] = make_float4(vv[i][4], vv[i][5], vv[i][6], vv[i][7]);
    }
#pragma unroll
    for (int j = 0; j < 8; j++) {
        int c = col0 + tx * 8 + j;
        __half hx[8];
#pragma unroll
        for (int i = 0; i < 8; i++) hx[i] = __float2half(vv[i][j]);
        *(uint4*)&CT[(size_t)c * NN + row0 + ty * 8] = *(uint4*)hx;
    }
}

// ============================================================
// Kernel 2: s1/s2 dot products (raw)
// ============================================================
__global__ __launch_bounds__(256) void s_kernel(
    const float* __restrict__ h, const float* __restrict__ a)
{
    int row = blockIdx.x * 8 + (threadIdx.x >> 5);
    int lane = threadIdx.x & 31;
    float a1 = 0.f, a2 = 0.f;
#pragma unroll
    for (int c = lane; c < FOUT; c += 32) {
        float hv = h[row * FOUT + c];
        a1 = fmaf(hv, a[c], a1);
        a2 = fmaf(hv, a[FOUT + c], a2);
    }
#pragma unroll
    for (int o = 16; o; o >>= 1) {
        a1 += __shfl_xor_sync(0xffffffffu, a1, o);
        a2 += __shfl_xor_sync(0xffffffffu, a2, o);
    }
    if (lane == 0) { g_s1r[row] = a1; g_s2r[row] = a2; }
}

// ============================================================
// Kernel 2b: S2MAX reduction (1 block, 1024 threads)
// ============================================================
__global__ __launch_bounds__(1024) void reduce_kernel(void)
{
    __shared__ float red[32];
    float mx = -3.0e38f;
#pragma unroll
    for (int i = 0; i < 8; i++) mx = fmaxf(mx, g_s2r[threadIdx.x + i * 1024]);
#pragma unroll
    for (int o = 16; o; o >>= 1) mx = fmaxf(mx, __shfl_xor_sync(0xffffffffu, mx, o));
    if ((threadIdx.x & 31) == 0) red[threadIdx.x >> 5] = mx;
    __syncthreads();
    if (threadIdx.x < 32) {
        float v = red[threadIdx.x];
#pragma unroll
        for (int o = 16; o; o >>= 1) v = fmaxf(v, __shfl_xor_sync(0xffffffffu, v, o));
        if (threadIdx.x == 0) g_s2max[0] = v;
    }
}

// ============================================================
// Kernel 2c: factor tables (32 blocks x 256 threads)
// ============================================================
__global__ __launch_bounds__(256) void table_kernel(void)
{
    const float S2MAX = g_s2max[0];
    int r = blockIdx.x * 256 + threadIdx.x;
    float s1 = g_s1r[r], s2 = g_s2r[r];
    float x = s1 + S2MAX;
    float m = fmaxf(x, 0.2f * x);
    g_e1[r] = make_float2(expf(s1 - m), expf(0.2f * s1 - m));
    g_e2[r] = make_float2(expf(s2), expf(0.2f * s2));
}

// ============================================================
// Kernel 3: fused attention GEMM, mma.sync fp16 m16n8k16.
//   8 warps x 32 rows x 17 nb, grid 128.
//   4-stage cp.async pipeline, prefetch distance 2, ONE sync/tile
//   (buffer written at iter t was last read at t-2; iter t-1's barrier
//    separates them).
// ============================================================
#define AT_THREADS 256
#define KT 32
#define ATILES 128
#define HSTRH 40                         // halves per Hs row
#define HS_BYTES (136 * HSTRH * 2)       // 10880
#define OFF_E2  (4 * HS_BYTES)           // 43520
#define AT_SMEM (OFF_E2 + 4096 * 8)      // 76288

__global__ void __launch_bounds__(AT_THREADS, 1) attn_kernel(void)
{
    extern __shared__ char dsm[];
    __half* HsB[4] = { (__half*)dsm, (__half*)(dsm + HS_BYTES),
                       (__half*)(dsm + 2 * HS_BYTES), (__half*)(dsm + 3 * HS_BYTES) };
    float2* e2sm = (float2*)(dsm + OFF_E2);

    const int tid = threadIdx.x, wid = tid >> 5, lane = tid & 31;
    const int q = lane >> 2, tc = lane & 3;
    const int rt = blockIdx.x >> 2, kh = (blockIdx.x >> 1) & 1, nh = blockIdx.x & 1;
    const int row0 = rt * 256, kbase = kh * 4096, nbase = nh * 128;

    // ---- stage e2 table (32 KB), first commit group ----
    {
        uint32_t dst = smem_u32(e2sm) + (uint32_t)tid * 16u;
        const float4* src = (const float4*)(g_e2 + kbase) + tid;
#pragma unroll
        for (int it = 0; it < 8; it++)
            asm volatile("cp.async.cg.shared.global [%0], [%1], 16;"
                         :: "r"(dst + it * 4096u), "l"(src + it * 256));
        asm volatile("cp.async.commit_group;");
    }
    // ---- ones rows (n local 128..135), all 4 buffers ----
    for (int i = tid; i < 8 * HSTRH / 2; i += AT_THREADS) {
        int r = 128 + i / (HSTRH / 2), c = i % (HSTRH / 2);
        ((uint32_t*)HsB[0])[(r * HSTRH) / 2 + c] = 0x3C003C00u;
        ((uint32_t*)HsB[1])[(r * HSTRH) / 2 + c] = 0x3C003C00u;
        ((uint32_t*)HsB[2])[(r * HSTRH) / 2 + c] = 0x3C003C00u;
        ((uint32_t*)HsB[3])[(r * HSTRH) / 2 + c] = 0x3C003C00u;
    }
    // ---- prefetch H tiles 0 and 1 ----
#pragma unroll
    for (int pt = 0; pt < 2; pt++) {
        uint32_t dstb = smem_u32(HsB[pt]);
        const __half* src = g_hT + (size_t)nbase * NN + kbase + pt * KT;
#pragma unroll
        for (int it = 0; it < 2; it++) {
            int i = tid + it * AT_THREADS;
            int n = i >> 2, c16 = i & 3;
            asm volatile("cp.async.cg.shared.global [%0], [%1], 16;"
                         :: "r"(dstb + (uint32_t)(n * HSTRH * 2 + c16 * 16)),
                            "l"(src + (size_t)n * NN + c16 * 8));
        }
        asm volatile("cp.async.commit_group;");
    }

    // ---- per-row constants (rows q + {0,8,16,24} of warp's 32) ----
    float f1p[4], f1n[4];
    const uint32_t* mrow[4];
#pragma unroll
    for (int r = 0; r < 4; r++) {
        int grow = row0 + wid * 32 + q + r * 8;
        float2 e = g_e1[grow];
        f1p[r] = e.x; f1n[r] = e.y;
        mrow[r] = g_mask + (size_t)grow * 256 + kh * 128;
    }
    uint32_t m0[4], m1[4];
#pragma unroll
    for (int r = 0; r < 4; r++) { m0[r] = mrow[r][0]; m1[r] = mrow[r][1]; }

    float acc[2][17][4];
#pragma unroll
    for (int g = 0; g < 2; g++)
#pragma unroll
        for (int nb = 0; nb < 17; nb++)
#pragma unroll
            for (int j = 0; j < 4; j++) acc[g][nb][j] = 0.f;

    for (int t = 0; t < ATILES; t++) {
        uint32_t m2[4] = {0, 0, 0, 0};
        if (t + 2 < ATILES) {
#pragma unroll
            for (int r = 0; r < 4; r++) m2[r] = mrow[r][t + 2];
            // prefetch tile t+2 into buffer (t+2)&3 (last read at t-2;
            // iter t-1's barrier separates)
            uint32_t dstb = smem_u32(HsB[(t + 2) & 3]);
            const __half* src = g_hT + (size_t)nbase * NN + kbase + (t + 2) * KT;
#pragma unroll
            for (int it = 0; it < 2; it++) {
                int i = tid + it * AT_THREADS;
                int n = i >> 2, c16 = i & 3;
                asm volatile("cp.async.cg.shared.global [%0], [%1], 16;"
                             :: "r"(dstb + (uint32_t)(n * HSTRH * 2 + c16 * 16)),
                                "l"(src + (size_t)n * NN + c16 * 8));
            }
            asm volatile("cp.async.commit_group;");
            asm volatile("cp.async.wait_group 2;");
        } else {
            asm volatile("cp.async.wait_group 0;");
        }
        __syncthreads();            // tile t visible to all; prior readers done

        const __half* Hb = HsB[t & 3];
        const int kl0 = t * KT;

#pragma unroll
        for (int c = 0; c < 2; c++) {           // two k16 chunks
            const int kc = c * 16 + 2 * tc;
            float2 e0 = e2sm[kl0 + kc];
            float2 e1 = e2sm[kl0 + kc + 1];
            float2 e8 = e2sm[kl0 + kc + 8];
            float2 e9 = e2sm[kl0 + kc + 9];
            const uint32_t b0m = 1u << kc, b1m = 2u << kc;
            const uint32_t b8m = 256u << kc, b9m = 512u << kc;

            uint32_t af[2][4];
#pragma unroll
            for (int r = 0; r < 4; r++) {
                float p0 = fmaxf(f1p[r] * e0.x, f1n[r] * e0.y);
                float p1 = fmaxf(f1p[r] * e1.x, f1n[r] * e1.y);
                float p8 = fmaxf(f1p[r] * e8.x, f1n[r] * e8.y);
                float p9 = fmaxf(f1p[r] * e9.x, f1n[r] * e9.y);
                p0 = (m0[r] & b0m) ? p0 : 0.f;
                p1 = (m0[r] & b1m) ? p1 : 0.f;
                p8 = (m0[r] & b8m) ? p8 : 0.f;
                p9 = (m0[r] & b9m) ? p9 : 0.f;
                af[r >> 1][(r & 1)]     = f16x2_pack(p1, p0);
                af[r >> 1][(r & 1) + 2] = f16x2_pack(p9, p8);
            }

            const __half* bp = Hb + q * HSTRH + c * 16 + 2 * tc;
#pragma unroll
            for (int nb = 0; nb < 17; nb++) {
                uint32_t b0 = *(const uint32_t*)(bp + nb * 8 * HSTRH);
                uint32_t b1 = *(const uint32_t*)(bp + nb * 8 * HSTRH + 8);
                asm volatile(
                    "mma.sync.aligned.m16n8k16.row.col.f32.f16.f16.f32 "
                    "{%0,%1,%2,%3}, {%4,%5,%6,%7}, {%8,%9}, {%0,%1,%2,%3};"
                    : "+f"(acc[0][nb][0]), "+f"(acc[0][nb][1]),
                      "+f"(acc[0][nb][2]), "+f"(acc[0][nb][3])
                    : "r"(af[0][0]), "r"(af[0][1]), "r"(af[0][2]), "r"(af[0][3]),
                      "r"(b0), "r"(b1));
                asm volatile(
                    "mma.sync.aligned.m16n8k16.row.col.f32.f16.f16.f32 "
                    "{%0,%1,%2,%3}, {%4,%5,%6,%7}, {%8,%9}, {%0,%1,%2,%3};"
                    : "+f"(acc[1][nb][0]), "+f"(acc[1][nb][1]),
                      "+f"(acc[1][nb][2]), "+f"(acc[1][nb][3])
                    : "r"(af[1][0]), "r"(af[1][1]), "r"(af[1][2]), "r"(af[1][3]),
                      "r"(b0), "r"(b1));
            }
        }

#pragma unroll
        for (int r = 0; r < 4; r++) { m0[r] = m1[r]; m1[r] = m2[r]; }
    }

    // ---- store partial D + z ----
    float* dp = g_dpart + (size_t)kh * NN * FOUT;
#pragma unroll
    for (int g = 0; g < 2; g++) {
        const int rlo = row0 + wid * 32 + g * 16 + q;
        const int rhi = rlo + 8;
#pragma unroll
        for (int nb = 0; nb < 16; nb++) {
            int c = nbase + nb * 8 + tc * 2;
            *(float2*)&dp[(size_t)rlo * FOUT + c] = make_float2(acc[g][nb][0], acc[g][nb][1]);
            *(float2*)&dp[(size_t)rhi * FOUT + c] = make_float2(acc[g][nb][2], acc[g][nb][3]);
        }
        if (nh == 0 && tc == 0) {
            g_z[kh * NN + rlo] = acc[g][16][0];
            g_z[kh * NN + rhi] = acc[g][16][2];
        }
    }
}

// ============================================================
// Kernel 4: combine K-split partials, normalize, ELU
// ============================================================
__global__ __launch_bounds__(256) void combine_kernel(float* __restrict__ out)
{
    int idx = blockIdx.x * 256 + threadIdx.x;
    const float4* d0 = (const float4*)g_dpart;
    const float4* d1 = d0 + (NN * FOUT / 4);
    float4 a = d0[idx], b = d1[idx];
    int row = idx >> 6;
    float inv = 1.0f / (g_z[row] + g_z[NN + row]);
    float4 o; float t;
    t = (a.x + b.x) * inv; o.x = (t > 0.f) ? t : expm1f(t);
    t = (a.y + b.y) * inv; o.y = (t > 0.f) ? t : expm1f(t);
    t = (a.z + b.z) * inv; o.z = (t > 0.f) ? t : expm1f(t);
    t = (a.w + b.w) * inv; o.w = (t > 0.f) ? t : expm1f(t);
    ((float4*)out)[idx] = o;
}

// ============================================================
// launch
// ============================================================
extern "C" void kernel_launch(void* const* d_in, const int* in_sizes, int n_in,
                              void* d_out, int out_size)
{
    const float* input = (const float*)d_in[0];   // [8192, 512]
    const int*   adj   = (const int*)  d_in[1];   // [8192, 8192]
    const float* W     = (const float*)d_in[2];   // [512, 256]
    const float* a     = (const float*)d_in[3];   // [512, 1]
    float* out = (float*)d_out;                   // [8192, 256]

    float* h;
    __half* hT;
    uint32_t* mask;
    cudaGetSymbolAddress((void**)&h, g_h);
    cudaGetSymbolAddress((void**)&hT, g_hT);
    cudaGetSymbolAddress((void**)&mask, g_mask);

    cudaFuncSetAttribute(attn_kernel, cudaFuncAttributeMaxDynamicSharedMemorySize, AT_SMEM);

    pack_kernel<<<NN, 256>>>(adj, mask);
    gemm_h_kernel<<<dim3(NN / G1_BM, FOUT / G1_BN), 256>>>(input, W, h, hT);
    s_kernel<<<NN / 8, 256>>>(h, a);
    reduce_kernel<<<1, 1024>>>();
    table_kernel<<<NN / 256, 256>>>();
    attn_kernel<<<128, AT_THREADS, AT_SMEM>>>();
    combine_kernel<<<NN * FOUT / 4 / 256, 256>>>(out);
}

// round 15
// speedup vs baseline: 1.4011x; 1.0830x over previous
#include <cuda_runtime.h>
#include <cuda_fp16.h>
#include <cstdint>

#define NN   8192
#define FIN  512
#define FOUT 256

// ---- scratch (static device memory; no allocation) ----
__device__ __align__(16) float g_h [NN * FOUT];          // fp32 h
__device__ __align__(16) __half g_hT[FOUT * NN];         // fp16 h transposed [n][j]
__device__ __align__(16) float g_s1r[NN];
__device__ __align__(16) float g_s2r[NN];
__device__ __align__(16) float g_s2max[1];
__device__ __align__(16) float2 g_e1[NN];                // (exp(s1-m), exp(.2 s1-m))
__device__ __align__(16) float2 g_e2[NN];                // (exp(s2), exp(.2 s2))
__device__ __align__(16) uint32_t g_mask[NN * 256];      // bit-packed adj
__device__ __align__(16) float g_dpart[2 * NN * FOUT];
__device__ __align__(16) float g_z[2 * NN];

// ============================================================
// helpers
// ============================================================
__device__ __forceinline__ uint32_t smem_u32(const void* p) {
    uint32_t a;
    asm("{ .reg .u64 t; cvta.to.shared.u64 t, %1; cvt.u32.u64 %0, t; }" : "=r"(a) : "l"(p));
    return a;
}
__device__ __forceinline__ unsigned long long pack2(float lo, float hi) {
    unsigned long long r;
    asm("mov.b64 %0, {%1, %2};" : "=l"(r) : "f"(lo), "f"(hi));
    return r;
}
__device__ __forceinline__ void unpack2(unsigned long long v, float& lo, float& hi) {
    asm("mov.b64 {%0, %1}, %2;" : "=f"(lo), "=f"(hi) : "l"(v));
}
__device__ __forceinline__ uint32_t f16x2_pack(float hi, float lo) {
    uint32_t r;
    asm("cvt.rn.f16x2.f32 %0, %1, %2;" : "=r"(r) : "f"(hi), "f"(lo));
    return r;
}

// ============================================================
// Kernel 0: bit-pack adjacency (DRAM-bound, ~33 us floor)
// ============================================================
__global__ __launch_bounds__(256) void pack_kernel(const int* __restrict__ adj,
                                                   uint32_t* __restrict__ mask)
{
    const int row = blockIdx.x;
    const int wid = threadIdx.x >> 5, lane = threadIdx.x & 31;
    const int* ar = adj + (size_t)row * NN;
#pragma unroll 4
    for (int i = 0; i < 32; i++) {
        int t = wid * 32 + i;
        int v = ar[t * 32 + lane];
        uint32_t b = __ballot_sync(0xffffffffu, v > 0);
        if (lane == 0) mask[row * 256 + t] = b;
    }
}

// ============================================================
// Kernel 1: h = input @ W (fp32, packed fma.rn.f32x2).
//   Epilogue emits fp32 h AND fp16 h^T.
// ============================================================
#define G1_BM 128
#define G1_BN 128
#define G1_BK 16

__global__ __launch_bounds__(256) void gemm_h_kernel(
    const float* __restrict__ A, const float* __restrict__ B,
    float* __restrict__ C, __half* __restrict__ CT)
{
    __shared__ float As[G1_BK][G1_BM + 4];
    __shared__ float Bs[G1_BK][G1_BN + 4];

    const int row0 = blockIdx.x * G1_BM;
    const int col0 = blockIdx.y * G1_BN;
    const int tid = threadIdx.x;
    const int tx = tid & 15, ty = tid >> 4;

    unsigned long long acc2[8][4];
#pragma unroll
    for (int i = 0; i < 8; i++)
#pragma unroll
        for (int j = 0; j < 4; j++) acc2[i][j] = 0ULL;

    for (int k0 = 0; k0 < FIN; k0 += G1_BK) {
#pragma unroll
        for (int it = 0; it < 2; it++) {
            int i = tid + it * 256;
            int r = i >> 2, c4 = i & 3;
            float4 v = *(const float4*)&A[(row0 + r) * FIN + k0 + c4 * 4];
            As[c4 * 4 + 0][r] = v.x;
            As[c4 * 4 + 1][r] = v.y;
            As[c4 * 4 + 2][r] = v.z;
            As[c4 * 4 + 3][r] = v.w;
        }
#pragma unroll
        for (int it = 0; it < 2; it++) {
            int i = tid + it * 256;
            int r = i >> 5, c4 = i & 31;
            float4 v = *(const float4*)&B[(k0 + r) * FOUT + col0 + c4 * 4];
            *(float4*)&Bs[r][c4 * 4] = v;
        }
        __syncthreads();

#pragma unroll
        for (int k = 0; k < G1_BK; k++) {
            float4 a0 = *(const float4*)&As[k][ty * 8];
            float4 a1 = *(const float4*)&As[k][ty * 8 + 4];
            float af[8] = {a0.x, a0.y, a0.z, a0.w, a1.x, a1.y, a1.z, a1.w};
            ulonglong2 b01 = ((const ulonglong2*)&Bs[k][tx * 8])[0];
            ulonglong2 b23 = ((const ulonglong2*)&Bs[k][tx * 8])[1];
            unsigned long long bb[4] = {b01.x, b01.y, b23.x, b23.y};
#pragma unroll
            for (int i = 0; i < 8; i++) {
                unsigned long long pa = pack2(af[i], af[i]);
#pragma unroll
                for (int j = 0; j < 4; j++)
                    asm("fma.rn.f32x2 %0, %1, %2, %0;"
                        : "+l"(acc2[i][j]) : "l"(pa), "l"(bb[j]));
            }
        }
        __syncthreads();
    }

    float vv[8][8];
#pragma unroll
    for (int i = 0; i < 8; i++) {
#pragma unroll
        for (int j2 = 0; j2 < 4; j2++)
            unpack2(acc2[i][j2], vv[i][j2 * 2], vv[i][j2 * 2 + 1]);
        int r = row0 + ty * 8 + i;
        *(float4*)&C[r * FOUT + col0 + tx * 8]     = make_float4(vv[i][0], vv[i][1], vv[i][2], vv[i][3]);
        *(float4*)&C[r * FOUT + col0 + tx * 8 + 4] = make_float4(vv[i][4], vv[i][5], vv[i][6], vv[i][7]);
    }
#pragma unroll
    for (int j = 0; j < 8; j++) {
        int c = col0 + tx * 8 + j;
        __half hx[8];
#pragma unroll
        for (int i = 0; i < 8; i++) hx[i] = __float2half(vv[i][j]);
        *(uint4*)&CT[(size_t)c * NN + row0 + ty * 8] = *(uint4*)hx;
    }
}

// ============================================================
// Kernel 2: s1/s2 dot products (raw)
// ============================================================
__global__ __launch_bounds__(256) void s_kernel(
    const float* __restrict__ h, const float* __restrict__ a)
{
    int row = blockIdx.x * 8 + (threadIdx.x >> 5);
    int lane = threadIdx.x & 31;
    float a1 = 0.f, a2 = 0.f;
#pragma unroll
    for (int c = lane; c < FOUT; c += 32) {
        float hv = h[row * FOUT + c];
        a1 = fmaf(hv, a[c], a1);
        a2 = fmaf(hv, a[FOUT + c], a2);
    }
#pragma unroll
    for (int o = 16; o; o >>= 1) {
        a1 += __shfl_xor_sync(0xffffffffu, a1, o);
        a2 += __shfl_xor_sync(0xffffffffu, a2, o);
    }
    if (lane == 0) { g_s1r[row] = a1; g_s2r[row] = a2; }
}

// ============================================================
// Kernel 2b: S2MAX reduction (1 block, 1024 threads)
// ============================================================
__global__ __launch_bounds__(1024) void reduce_kernel(void)
{
    __shared__ float red[32];
    float mx = -3.0e38f;
#pragma unroll
    for (int i = 0; i < 8; i++) mx = fmaxf(mx, g_s2r[threadIdx.x + i * 1024]);
#pragma unroll
    for (int o = 16; o; o >>= 1) mx = fmaxf(mx, __shfl_xor_sync(0xffffffffu, mx, o));
    if ((threadIdx.x & 31) == 0) red[threadIdx.x >> 5] = mx;
    __syncthreads();
    if (threadIdx.x < 32) {
        float v = red[threadIdx.x];
#pragma unroll
        for (int o = 16; o; o >>= 1) v = fmaxf(v, __shfl_xor_sync(0xffffffffu, v, o));
        if (threadIdx.x == 0) g_s2max[0] = v;
    }
}

// ============================================================
// Kernel 2c: factor tables (32 blocks x 256 threads)
// ============================================================
__global__ __launch_bounds__(256) void table_kernel(void)
{
    const float S2MAX = g_s2max[0];
    int r = blockIdx.x * 256 + threadIdx.x;
    float s1 = g_s1r[r], s2 = g_s2r[r];
    float x = s1 + S2MAX;
    float m = fmaxf(x, 0.2f * x);
    g_e1[r] = make_float2(expf(s1 - m), expf(0.2f * s1 - m));
    g_e2[r] = make_float2(expf(s2), expf(0.2f * s2));
}

// ============================================================
// Kernel 3: fused attention GEMM, mma.sync fp16 m16n8k16.
//   8 warps x 32 rows x 17 nb, grid 128.
//   4-stage cp.async pipeline, one sync/tile.
//   B operands via ldmatrix.x4 (2 n-blocks per LDSM, conflict-free at
//   80B row stride); z-column B is the constant 1.0 fragment (no smem).
// ============================================================
#define AT_THREADS 256
#define KT 32
#define ATILES 128
#define HSTRH 40                         // halves per Hs row (80 B)
#define HS_BYTES (128 * HSTRH * 2)       // 10240
#define OFF_E2  (4 * HS_BYTES)           // 40960
#define AT_SMEM (OFF_E2 + 4096 * 8)      // 73728

#define MMA_F16(accv, a0, a1, a2, a3, b0, b1) \
    asm volatile( \
        "mma.sync.aligned.m16n8k16.row.col.f32.f16.f16.f32 " \
        "{%0,%1,%2,%3}, {%4,%5,%6,%7}, {%8,%9}, {%0,%1,%2,%3};" \
        : "+f"((accv)[0]), "+f"((accv)[1]), "+f"((accv)[2]), "+f"((accv)[3]) \
        : "r"(a0), "r"(a1), "r"(a2), "r"(a3), "r"(b0), "r"(b1))

__global__ void __launch_bounds__(AT_THREADS, 1) attn_kernel(void)
{
    extern __shared__ char dsm[];
    __half* HsB[4] = { (__half*)dsm, (__half*)(dsm + HS_BYTES),
                       (__half*)(dsm + 2 * HS_BYTES), (__half*)(dsm + 3 * HS_BYTES) };
    float2* e2sm = (float2*)(dsm + OFF_E2);

    const int tid = threadIdx.x, wid = tid >> 5, lane = tid & 31;
    const int q = lane >> 2, tc = lane & 3;
    const int rt = blockIdx.x >> 2, kh = (blockIdx.x >> 1) & 1, nh = blockIdx.x & 1;
    const int row0 = rt * 256, kbase = kh * 4096, nbase = nh * 128;

    // ldmatrix per-lane row-address offset:
    //   m = lane>>3 selects matrix {(nb0,klo),(nb0,khi),(nb1,klo),(nb1,khi)},
    //   r = lane&7 is the row (n) within the 8x8 matrix.
    const int lm_m = lane >> 3, lm_r = lane & 7;
    const uint32_t laneOff = (uint32_t)(((lm_m >> 1) * 8 + lm_r) * (HSTRH * 2)
                                        + (lm_m & 1) * 16);
    const uint32_t ONE2 = 0x3C003C00u;

    // ---- stage e2 table (32 KB), first commit group ----
    {
        uint32_t dst = smem_u32(e2sm) + (uint32_t)tid * 16u;
        const float4* src = (const float4*)(g_e2 + kbase) + tid;
#pragma unroll
        for (int it = 0; it < 8; it++)
            asm volatile("cp.async.cg.shared.global [%0], [%1], 16;"
                         :: "r"(dst + it * 4096u), "l"(src + it * 256));
        asm volatile("cp.async.commit_group;");
    }
    // ---- prefetch H tiles 0 and 1 ----
#pragma unroll
    for (int pt = 0; pt < 2; pt++) {
        uint32_t dstb = smem_u32(HsB[pt]);
        const __half* src = g_hT + (size_t)nbase * NN + kbase + pt * KT;
#pragma unroll
        for (int it = 0; it < 2; it++) {
            int i = tid + it * AT_THREADS;
            int n = i >> 2, c16 = i & 3;
            asm volatile("cp.async.cg.shared.global [%0], [%1], 16;"
                         :: "r"(dstb + (uint32_t)(n * HSTRH * 2 + c16 * 16)),
                            "l"(src + (size_t)n * NN + c16 * 8));
        }
        asm volatile("cp.async.commit_group;");
    }

    // ---- per-row constants (rows q + {0,8,16,24} of warp's 32) ----
    float f1p[4], f1n[4];
    const uint32_t* mrow[4];
#pragma unroll
    for (int r = 0; r < 4; r++) {
        int grow = row0 + wid * 32 + q + r * 8;
        float2 e = g_e1[grow];
        f1p[r] = e.x; f1n[r] = e.y;
        mrow[r] = g_mask + (size_t)grow * 256 + kh * 128;
    }
    uint32_t m0[4], m1[4];
#pragma unroll
    for (int r = 0; r < 4; r++) { m0[r] = mrow[r][0]; m1[r] = mrow[r][1]; }

    float acc[2][17][4];
#pragma unroll
    for (int g = 0; g < 2; g++)
#pragma unroll
        for (int nb = 0; nb < 17; nb++)
#pragma unroll
            for (int j = 0; j < 4; j++) acc[g][nb][j] = 0.f;

    for (int t = 0; t < ATILES; t++) {
        uint32_t m2[4] = {0, 0, 0, 0};
        if (t + 2 < ATILES) {
#pragma unroll
            for (int r = 0; r < 4; r++) m2[r] = mrow[r][t + 2];
            uint32_t dstb = smem_u32(HsB[(t + 2) & 3]);
            const __half* src = g_hT + (size_t)nbase * NN + kbase + (t + 2) * KT;
#pragma unroll
            for (int it = 0; it < 2; it++) {
                int i = tid + it * AT_THREADS;
                int n = i >> 2, c16 = i & 3;
                asm volatile("cp.async.cg.shared.global [%0], [%1], 16;"
                             :: "r"(dstb + (uint32_t)(n * HSTRH * 2 + c16 * 16)),
                                "l"(src + (size_t)n * NN + c16 * 8));
            }
            asm volatile("cp.async.commit_group;");
            asm volatile("cp.async.wait_group 2;");
        } else {
            asm volatile("cp.async.wait_group 0;");
        }
        __syncthreads();            // tile t visible; prior readers done

        const uint32_t bufB = smem_u32(HsB[t & 3]) + laneOff;
        const int kl0 = t * KT;

#pragma unroll
        for (int c = 0; c < 2; c++) {           // two k16 chunks
            const int kc = c * 16 + 2 * tc;
            float2 e0 = e2sm[kl0 + kc];
            float2 e1 = e2sm[kl0 + kc + 1];
            float2 e8 = e2sm[kl0 + kc + 8];
            float2 e9 = e2sm[kl0 + kc + 9];
            const uint32_t b0m = 1u << kc, b1m = 2u << kc;
            const uint32_t b8m = 256u << kc, b9m = 512u << kc;

            uint32_t af[2][4];
#pragma unroll
            for (int r = 0; r < 4; r++) {
                float p0 = fmaxf(f1p[r] * e0.x, f1n[r] * e0.y);
                float p1 = fmaxf(f1p[r] * e1.x, f1n[r] * e1.y);
                float p8 = fmaxf(f1p[r] * e8.x, f1n[r] * e8.y);
                float p9 = fmaxf(f1p[r] * e9.x, f1n[r] * e9.y);
                p0 = (m0[r] & b0m) ? p0 : 0.f;
                p1 = (m0[r] & b1m) ? p1 : 0.f;
                p8 = (m0[r] & b8m) ? p8 : 0.f;
                p9 = (m0[r] & b9m) ? p9 : 0.f;
                af[r >> 1][(r & 1)]     = f16x2_pack(p1, p0);
                af[r >> 1][(r & 1) + 2] = f16x2_pack(p9, p8);
            }

            const uint32_t lmb = bufB + c * 32;
#pragma unroll
            for (int nbp = 0; nbp < 8; nbp++) {
                uint32_t b0, b1, b2, b3;
                asm volatile(
                    "ldmatrix.sync.aligned.m8n8.x4.shared.b16 {%0,%1,%2,%3}, [%4];"
                    : "=r"(b0), "=r"(b1), "=r"(b2), "=r"(b3)
                    : "r"(lmb + (uint32_t)(nbp * 16 * HSTRH * 2)));
                MMA_F16(acc[0][nbp * 2],     af[0][0], af[0][1], af[0][2], af[0][3], b0, b1);
                MMA_F16(acc[1][nbp * 2],     af[1][0], af[1][1], af[1][2], af[1][3], b0, b1);
                MMA_F16(acc[0][nbp * 2 + 1], af[0][0], af[0][1], af[0][2], af[0][3], b2, b3);
                MMA_F16(acc[1][nbp * 2 + 1], af[1][0], af[1][1], af[1][2], af[1][3], b2, b3);
            }
            // z column: B == all-ones (constant fragment, no smem)
            MMA_F16(acc[0][16], af[0][0], af[0][1], af[0][2], af[0][3], ONE2, ONE2);
            MMA_F16(acc[1][16], af[1][0], af[1][1], af[1][2], af[1][3], ONE2, ONE2);
        }

#pragma unroll
        for (int r = 0; r < 4; r++) { m0[r] = m1[r]; m1[r] = m2[r]; }
    }

    // ---- store partial D + z ----
    float* dp = g_dpart + (size_t)kh * NN * FOUT;
#pragma unroll
    for (int g = 0; g < 2; g++) {
        const int rlo = row0 + wid * 32 + g * 16 + q;
        const int rhi = rlo + 8;
#pragma unroll
        for (int nb = 0; nb < 16; nb++) {
            int c = nbase + nb * 8 + tc * 2;
            *(float2*)&dp[(size_t)rlo * FOUT + c] = make_float2(acc[g][nb][0], acc[g][nb][1]);
            *(float2*)&dp[(size_t)rhi * FOUT + c] = make_float2(acc[g][nb][2], acc[g][nb][3]);
        }
        if (nh == 0 && tc == 0) {
            g_z[kh * NN + rlo] = acc[g][16][0];
            g_z[kh * NN + rhi] = acc[g][16][2];
        }
    }
}

// ============================================================
// Kernel 4: combine K-split partials, normalize, ELU
// ============================================================
__global__ __launch_bounds__(256) void combine_kernel(float* __restrict__ out)
{
    int idx = blockIdx.x * 256 + threadIdx.x;
    const float4* d0 = (const float4*)g_dpart;
    const float4* d1 = d0 + (NN * FOUT / 4);
    float4 a = d0[idx], b = d1[idx];
    int row = idx >> 6;
    float inv = 1.0f / (g_z[row] + g_z[NN + row]);
    float4 o; float t;
    t = (a.x + b.x) * inv; o.x = (t > 0.f) ? t : expm1f(t);
    t = (a.y + b.y) * inv; o.y = (t > 0.f) ? t : expm1f(t);
    t = (a.z + b.z) * inv; o.z = (t > 0.f) ? t : expm1f(t);
    t = (a.w + b.w) * inv; o.w = (t > 0.f) ? t : expm1f(t);
    ((float4*)out)[idx] = o;
}

// ============================================================
// launch
// ============================================================
extern "C" void kernel_launch(void* const* d_in, const int* in_sizes, int n_in,
                              void* d_out, int out_size)
{
    const float* input = (const float*)d_in[0];   // [8192, 512]
    const int*   adj   = (const int*)  d_in[1];   // [8192, 8192]
    const float* W     = (const float*)d_in[2];   // [512, 256]
    const float* a     = (const float*)d_in[3];   // [512, 1]
    float* out = (float*)d_out;                   // [8192, 256]

    float* h;
    __half* hT;
    uint32_t* mask;
    cudaGetSymbolAddress((void**)&h, g_h);
    cudaGetSymbolAddress((void**)&hT, g_hT);
    cudaGetSymbolAddress((void**)&mask, g_mask);

    cudaFuncSetAttribute(attn_kernel, cudaFuncAttributeMaxDynamicSharedMemorySize, AT_SMEM);

    pack_kernel<<<NN, 256>>>(adj, mask);
    gemm_h_kernel<<<dim3(NN / G1_BM, FOUT / G1_BN), 256>>>(input, W, h, hT);
    s_kernel<<<NN / 8, 256>>>(h, a);
    reduce_kernel<<<1, 1024>>>();
    table_kernel<<<NN / 256, 256>>>();
    attn_kernel<<<128, AT_THREADS, AT_SMEM>>>();
    combine_kernel<<<NN * FOUT / 4 / 256, 256>>>(out);
}